// round 1
// baseline (speedup 1.0000x reference)
#include <cuda_runtime.h>

// ---------------------------------------------------------------------------
// UnpoolWithSkip:
//   h = relu(BN(feat @ W_proj + b_proj))          [65536, 256]
//   s = relu(BN(skip @ W_skip + b_skip))          [262144, 256]
//   out = h[cluster] + s                          [262144, 256]
//
// Pipeline (all fp32, CUDA cores — baseline for profiling):
//   K0 zero_stats
//   K1 sgemm_bias  : g_h = feat @ W_proj + b_proj
//   K2 col_reduce  : per-channel sum / sumsq of g_h
//   K3 sgemm_bias  : g_s = skip @ W_skip + b_skip
//   K4 col_reduce  : per-channel sum / sumsq of g_s
//   K5 finalize    : BN -> per-channel affine a*x + b
//   K6 fuse        : out[n] = relu(a_p*g_h[cluster[n]]+b_p) + relu(a_s*g_s[n]+b_s)
// ---------------------------------------------------------------------------

#define EPS 1e-5f

static constexpr int N_IN   = 65536;
static constexpr int N_OUT  = 262144;
static constexpr int C_OUT  = 256;

// Scratch (allocation-free rule: __device__ globals)
__device__ float g_h[(size_t)N_IN  * C_OUT];   //  67 MB
__device__ float g_s[(size_t)N_OUT * C_OUT];   // 268 MB
__device__ float g_sum_p[C_OUT], g_ssq_p[C_OUT];
__device__ float g_sum_s[C_OUT], g_ssq_s[C_OUT];
__device__ float g_a_p[C_OUT], g_b_p[C_OUT];
__device__ float g_a_s[C_OUT], g_b_s[C_OUT];

__global__ void zero_stats_kernel() {
    int c = threadIdx.x;
    g_sum_p[c] = 0.f; g_ssq_p[c] = 0.f;
    g_sum_s[c] = 0.f; g_ssq_s[c] = 0.f;
}

// ---------------------------------------------------------------------------
// SGEMM: C[M,N] = A[M,K] @ B[K,N] + bias[N]   (row-major, M%128==0, N%128==0,
// K%16==0). 128x128 tile, BK=16, 256 threads, 8x8 per-thread microtile.
// ---------------------------------------------------------------------------
__global__ __launch_bounds__(256) void sgemm_bias_kernel(
    const float* __restrict__ A, const float* __restrict__ B,
    const float* __restrict__ bias, float* __restrict__ C,
    int M, int N, int K)
{
    constexpr int BM = 128, BN = 128, BK = 16;
    __shared__ float As[BK][BM + 4];   // transposed A tile (padded)
    __shared__ float Bs[BK][BN];

    const int tid = threadIdx.x;
    const int m0 = blockIdx.y * BM;
    const int n0 = blockIdx.x * BN;
    const int tx = tid & 15;           // 0..15 -> N microtile
    const int ty = tid >> 4;           // 0..15 -> M microtile

    float acc[8][8] = {};

    for (int k0 = 0; k0 < K; k0 += BK) {
        // Load A tile: 128 rows x 16 cols = 512 float4 (4 per row)
        // Load B tile:  16 rows x 128 cols = 512 float4 (32 per row)
        #pragma unroll
        for (int i = 0; i < 2; i++) {
            int idx = tid + i * 256;
            int ar = idx >> 2, ac = (idx & 3) << 2;
            float4 av = *(const float4*)&A[(size_t)(m0 + ar) * K + k0 + ac];
            As[ac + 0][ar] = av.x;
            As[ac + 1][ar] = av.y;
            As[ac + 2][ar] = av.z;
            As[ac + 3][ar] = av.w;
            int br = idx >> 5, bc = (idx & 31) << 2;
            *(float4*)&Bs[br][bc] =
                *(const float4*)&B[(size_t)(k0 + br) * N + n0 + bc];
        }
        __syncthreads();

        #pragma unroll
        for (int k = 0; k < BK; k++) {
            float a[8], b[8];
            float4 a0 = *(const float4*)&As[k][ty * 8];
            float4 a1 = *(const float4*)&As[k][ty * 8 + 4];
            a[0]=a0.x; a[1]=a0.y; a[2]=a0.z; a[3]=a0.w;
            a[4]=a1.x; a[5]=a1.y; a[6]=a1.z; a[7]=a1.w;
            float4 b0 = *(const float4*)&Bs[k][tx * 8];
            float4 b1 = *(const float4*)&Bs[k][tx * 8 + 4];
            b[0]=b0.x; b[1]=b0.y; b[2]=b0.z; b[3]=b0.w;
            b[4]=b1.x; b[5]=b1.y; b[6]=b1.z; b[7]=b1.w;
            #pragma unroll
            for (int i = 0; i < 8; i++)
                #pragma unroll
                for (int j = 0; j < 8; j++)
                    acc[i][j] = fmaf(a[i], b[j], acc[i][j]);
        }
        __syncthreads();
    }

    // Epilogue: add bias, store
    #pragma unroll
    for (int i = 0; i < 8; i++) {
        int row = m0 + ty * 8 + i;
        #pragma unroll
        for (int j = 0; j < 8; j += 4) {
            int col = n0 + tx * 8 + j;
            float4 v;
            v.x = acc[i][j + 0] + bias[col + 0];
            v.y = acc[i][j + 1] + bias[col + 1];
            v.z = acc[i][j + 2] + bias[col + 2];
            v.w = acc[i][j + 3] + bias[col + 3];
            *(float4*)&C[(size_t)row * N + col] = v;
        }
    }
}

// ---------------------------------------------------------------------------
// Per-channel sum & sum-of-squares over rows of X[Nrows, 256].
// One thread per channel; CTAs split rows; atomic partial reduction.
// ---------------------------------------------------------------------------
__global__ __launch_bounds__(256) void col_reduce_kernel(
    const float* __restrict__ X, int Nrows,
    float* __restrict__ sum, float* __restrict__ ssq)
{
    int c = threadIdx.x;
    int rows_per_cta = Nrows / gridDim.x;
    int r0 = blockIdx.x * rows_per_cta;
    int r1 = r0 + rows_per_cta;
    float s = 0.f, q = 0.f;
    for (int r = r0; r < r1; r++) {
        float v = X[(size_t)r * C_OUT + c];
        s += v;
        q = fmaf(v, v, q);
    }
    atomicAdd(&sum[c], s);
    atomicAdd(&ssq[c], q);
}

// BN(x) = (x-m)*rsqrt(v+eps)*gamma + beta  ==  a*x + b
__global__ void finalize_kernel(
    const float* __restrict__ gamma_p, const float* __restrict__ beta_p,
    const float* __restrict__ gamma_s, const float* __restrict__ beta_s)
{
    int c = threadIdx.x;
    {
        float m = g_sum_p[c] * (1.f / N_IN);
        float v = g_ssq_p[c] * (1.f / N_IN) - m * m;
        float a = gamma_p[c] * rsqrtf(v + EPS);
        g_a_p[c] = a;
        g_b_p[c] = beta_p[c] - m * a;
    }
    {
        float m = g_sum_s[c] * (1.f / N_OUT);
        float v = g_ssq_s[c] * (1.f / N_OUT) - m * m;
        float a = gamma_s[c] * rsqrtf(v + EPS);
        g_a_s[c] = a;
        g_b_s[c] = beta_s[c] - m * a;
    }
}

// ---------------------------------------------------------------------------
// out[n,c] = relu(a_p*g_h[cluster[n],c]+b_p) + relu(a_s*g_s[n,c]+b_s)
// One thread per float4 (4 channels). 64 float4 per output row.
// ---------------------------------------------------------------------------
__global__ __launch_bounds__(256) void fuse_out_kernel(
    const int* __restrict__ cluster, float* __restrict__ out)
{
    int idx = blockIdx.x * 256 + threadIdx.x;   // N_OUT*64 total
    int n  = idx >> 6;
    int c4 = (idx & 63) << 2;
    int k  = __ldg(&cluster[n]);

    float4 h  = *(const float4*)&g_h[(size_t)k * C_OUT + c4];
    float4 sv = *(const float4*)&g_s[(size_t)n * C_OUT + c4];
    float4 ap = *(const float4*)&g_a_p[c4];
    float4 bp = *(const float4*)&g_b_p[c4];
    float4 as_ = *(const float4*)&g_a_s[c4];
    float4 bs_ = *(const float4*)&g_b_s[c4];

    float4 o;
    o.x = fmaxf(fmaf(ap.x, h.x, bp.x), 0.f) + fmaxf(fmaf(as_.x, sv.x, bs_.x), 0.f);
    o.y = fmaxf(fmaf(ap.y, h.y, bp.y), 0.f) + fmaxf(fmaf(as_.y, sv.y, bs_.y), 0.f);
    o.z = fmaxf(fmaf(ap.z, h.z, bp.z), 0.f) + fmaxf(fmaf(as_.z, sv.z, bs_.z), 0.f);
    o.w = fmaxf(fmaf(ap.w, h.w, bp.w), 0.f) + fmaxf(fmaf(as_.w, sv.w, bs_.w), 0.f);
    *(float4*)&out[(size_t)n * C_OUT + c4] = o;
}

// ---------------------------------------------------------------------------
extern "C" void kernel_launch(void* const* d_in, const int* in_sizes, int n_in,
                              void* d_out, int out_size)
{
    const float* feat    = (const float*)d_in[0];   // [65536, 512]
    const float* skip    = (const float*)d_in[1];   // [262144, 256]
    const int*   cluster = (const int*)  d_in[2];   // [262144]
    const float* W_proj  = (const float*)d_in[3];   // [512, 256]
    const float* b_proj  = (const float*)d_in[4];
    const float* gamma_p = (const float*)d_in[5];
    const float* beta_p  = (const float*)d_in[6];
    const float* W_skip  = (const float*)d_in[7];   // [256, 256]
    const float* b_skip  = (const float*)d_in[8];
    const float* gamma_s = (const float*)d_in[9];
    const float* beta_s  = (const float*)d_in[10];
    float* out = (float*)d_out;

    float* h_ptr; cudaGetSymbolAddress((void**)&h_ptr, g_h);
    float* s_ptr; cudaGetSymbolAddress((void**)&s_ptr, g_s);
    float* sum_p; cudaGetSymbolAddress((void**)&sum_p, g_sum_p);
    float* ssq_p; cudaGetSymbolAddress((void**)&ssq_p, g_ssq_p);
    float* sum_s; cudaGetSymbolAddress((void**)&sum_s, g_sum_s);
    float* ssq_s; cudaGetSymbolAddress((void**)&ssq_s, g_ssq_s);

    zero_stats_kernel<<<1, 256>>>();

    // GEMM1: g_h = feat @ W_proj + b_proj   (M=65536, N=256, K=512)
    sgemm_bias_kernel<<<dim3(C_OUT / 128, N_IN / 128), 256>>>(
        feat, W_proj, b_proj, h_ptr, N_IN, C_OUT, 512);

    col_reduce_kernel<<<256, 256>>>(h_ptr, N_IN, sum_p, ssq_p);

    // GEMM2: g_s = skip @ W_skip + b_skip   (M=262144, N=256, K=256)
    sgemm_bias_kernel<<<dim3(C_OUT / 128, N_OUT / 128), 256>>>(
        skip, W_skip, b_skip, s_ptr, N_OUT, C_OUT, 256);

    col_reduce_kernel<<<512, 256>>>(s_ptr, N_OUT, sum_s, ssq_s);

    finalize_kernel<<<1, 256>>>(gamma_p, beta_p, gamma_s, beta_s);

    fuse_out_kernel<<<(N_OUT * 64) / 256, 256>>>(cluster, out);
}

// round 3
// speedup vs baseline: 1.7453x; 1.7453x over previous
#include <cuda_runtime.h>
#include <cstdint>

// ---------------------------------------------------------------------------
// UnpoolWithSkip — tf32 mma.sync GEMMs (arch-independent PTX; harness compiles
// at compute_103 so tcgen05 is unavailable) + fused BN-stat epilogue.
//   h = relu(BN(feat @ W_proj + b_proj))          [65536, 256]
//   s = relu(BN(skip @ W_skip + b_skip))          [262144, 256]
//   out = h[cluster] + s                          [262144, 256]
// ---------------------------------------------------------------------------

#define EPS 1e-5f

static constexpr int N_IN  = 65536;
static constexpr int N_OUT = 262144;
static constexpr int C     = 256;

// Scratch (__device__ globals; no allocation allowed)
__device__ float g_h[(size_t)N_IN  * C];
__device__ float g_s[(size_t)N_OUT * C];
__device__ float g_wt_proj[(size_t)C * 512];
__device__ float g_wt_skip[(size_t)C * 256];
__device__ float g_sum_p[C], g_ssq_p[C];
__device__ float g_sum_s[C], g_ssq_s[C];
__device__ float g_a_p[C], g_b_p[C];
__device__ float g_a_s[C], g_b_s[C];

// ---------------------------------------------------------------------------
__device__ __forceinline__ uint32_t smem_u32(const void* p) {
    uint32_t a;
    asm("{ .reg .u64 t; cvta.to.shared.u64 t, %1; cvt.u32.u64 %0, t; }"
        : "=r"(a) : "l"(p));
    return a;
}
__device__ __forceinline__ uint32_t f2tf32(float x) {
    uint32_t u;
    asm("cvt.rna.tf32.f32 %0, %1;" : "=r"(u) : "f"(x));
    return u;
}
__device__ __forceinline__ void mma_tf32(float* c, const uint32_t* a, const uint32_t* b) {
    asm volatile(
        "mma.sync.aligned.m16n8k8.row.col.f32.tf32.tf32.f32 "
        "{%0,%1,%2,%3}, {%4,%5,%6,%7}, {%8,%9}, {%0,%1,%2,%3};"
        : "+f"(c[0]), "+f"(c[1]), "+f"(c[2]), "+f"(c[3])
        : "r"(a[0]), "r"(a[1]), "r"(a[2]), "r"(a[3]), "r"(b[0]), "r"(b[1]));
}

// ---------------------------------------------------------------------------
// Small kernels
// ---------------------------------------------------------------------------
__global__ void zero_stats_kernel() {
    int c = threadIdx.x;
    g_sum_p[c] = 0.f; g_ssq_p[c] = 0.f;
    g_sum_s[c] = 0.f; g_ssq_s[c] = 0.f;
}

// Wt[n*K+k] = W[k*N+n]; grid (N/32, K/32), block (32,8)
__global__ void transpose_w_kernel(const float* __restrict__ W,
                                   float* __restrict__ Wt, int K, int N) {
    __shared__ float t[32][33];
    int n0 = blockIdx.x * 32, k0 = blockIdx.y * 32;
    int tx = threadIdx.x, ty = threadIdx.y;
    #pragma unroll
    for (int i = 0; i < 32; i += 8)
        t[ty + i][tx] = W[(size_t)(k0 + ty + i) * N + n0 + tx];
    __syncthreads();
    #pragma unroll
    for (int i = 0; i < 32; i += 8)
        Wt[(size_t)(n0 + ty + i) * K + k0 + tx] = t[tx][ty + i];
}

__global__ void finalize_kernel(
    const float* __restrict__ gamma_p, const float* __restrict__ beta_p,
    const float* __restrict__ gamma_s, const float* __restrict__ beta_s)
{
    int c = threadIdx.x;
    {
        float m = g_sum_p[c] * (1.f / N_IN);
        float v = g_ssq_p[c] * (1.f / N_IN) - m * m;
        float a = gamma_p[c] * rsqrtf(v + EPS);
        g_a_p[c] = a; g_b_p[c] = beta_p[c] - m * a;
    }
    {
        float m = g_sum_s[c] * (1.f / N_OUT);
        float v = g_ssq_s[c] * (1.f / N_OUT) - m * m;
        float a = gamma_s[c] * rsqrtf(v + EPS);
        g_a_s[c] = a; g_b_s[c] = beta_s[c] - m * a;
    }
}

__global__ __launch_bounds__(256) void fuse_out_kernel(
    const int* __restrict__ cluster, float* __restrict__ out)
{
    int idx = blockIdx.x * 256 + threadIdx.x;
    int n  = idx >> 6;
    int c4 = (idx & 63) << 2;
    int k  = __ldg(&cluster[n]);

    float4 h  = *(const float4*)&g_h[(size_t)k * C + c4];
    float4 sv = *(const float4*)&g_s[(size_t)n * C + c4];
    float4 ap = *(const float4*)&g_a_p[c4];
    float4 bp = *(const float4*)&g_b_p[c4];
    float4 as_ = *(const float4*)&g_a_s[c4];
    float4 bs_ = *(const float4*)&g_b_s[c4];

    float4 o;
    o.x = fmaxf(fmaf(ap.x, h.x, bp.x), 0.f) + fmaxf(fmaf(as_.x, sv.x, bs_.x), 0.f);
    o.y = fmaxf(fmaf(ap.y, h.y, bp.y), 0.f) + fmaxf(fmaf(as_.y, sv.y, bs_.y), 0.f);
    o.z = fmaxf(fmaf(ap.z, h.z, bp.z), 0.f) + fmaxf(fmaf(as_.z, sv.z, bs_.z), 0.f);
    o.w = fmaxf(fmaf(ap.w, h.w, bp.w), 0.f) + fmaxf(fmaf(as_.w, sv.w, bs_.w), 0.f);
    *(float4*)&out[(size_t)n * C + c4] = o;
}

// ---------------------------------------------------------------------------
// tf32 mma.sync GEMM: C[M,256] = A[M,K] @ Bt[256,K]^T + bias, + per-channel
// sum/sumsq. Tile 128x128, BK=32, 256 threads (warps 4x2 -> 32x64 each).
// cp.async double-buffered. Grid (M/128, 2).
// ---------------------------------------------------------------------------
static constexpr int PAD_STRIDE = 36;                 // floats per smem row
static constexpr int TILE_FLOATS = 128 * PAD_STRIDE;  // 4608
static constexpr uint32_t A_BYTES = TILE_FLOATS * 4;  // 18432
static constexpr uint32_t STAGE_BYTES = A_BYTES * 2;  // A + B
static constexpr uint32_t SMEM_BYTES = STAGE_BYTES * 2;

__device__ __forceinline__ void load_tile_async(
    const float* __restrict__ A, const float* __restrict__ Bt, int K,
    int m0, int n0, int kt, uint32_t sbase, int tid)
{
    #pragma unroll
    for (int p = 0; p < 4; p++) {
        int idx = tid + p * 256;
        int row = idx >> 3, ch = idx & 7;
        const float* ga = A + (size_t)(m0 + row) * K + kt * 32 + ch * 4;
        uint32_t sa = sbase + row * (PAD_STRIDE * 4) + ch * 16;
        asm volatile("cp.async.cg.shared.global [%0], [%1], 16;"
                     :: "r"(sa), "l"(ga) : "memory");
        const float* gb = Bt + (size_t)(n0 + row) * K + kt * 32 + ch * 4;
        uint32_t sb = sbase + A_BYTES + row * (PAD_STRIDE * 4) + ch * 16;
        asm volatile("cp.async.cg.shared.global [%0], [%1], 16;"
                     :: "r"(sb), "l"(gb) : "memory");
    }
}

__global__ __launch_bounds__(256) void mma_gemm_kernel(
    const float* __restrict__ A, const float* __restrict__ Bt,
    const float* __restrict__ bias, float* __restrict__ Cout,
    int K, float* __restrict__ sum, float* __restrict__ ssq)
{
    extern __shared__ char smem_raw[];
    __shared__ float ssum[128], sssq[128];

    const int tid  = threadIdx.x;
    const int lane = tid & 31;
    const int wid  = tid >> 5;
    const int wm   = wid & 3;          // 0..3 -> M offset 32*wm
    const int wn   = wid >> 2;         // 0..1 -> N offset 64*wn
    const int g    = lane >> 2;        // 0..7
    const int t    = lane & 3;         // 0..3

    const int m0 = blockIdx.x * 128;
    const int n0 = blockIdx.y * 128;

    const uint32_t sbase = smem_u32(smem_raw);

    if (tid < 128) { ssum[tid] = 0.f; sssq[tid] = 0.f; }

    float acc[2][8][4];
    #pragma unroll
    for (int i = 0; i < 2; i++)
        #pragma unroll
        for (int j = 0; j < 8; j++)
            #pragma unroll
            for (int q = 0; q < 4; q++) acc[i][j][q] = 0.f;

    const int KT = K >> 5;

    load_tile_async(A, Bt, K, m0, n0, 0, sbase, tid);
    asm volatile("cp.async.commit_group;" ::: "memory");

    const int mw = wm * 32;
    const int nw = wn * 64;

    for (int kt = 0; kt < KT; kt++) {
        const int buf = kt & 1;
        if (kt + 1 < KT) {
            load_tile_async(A, Bt, K, m0, n0, kt + 1,
                            sbase + (buf ^ 1) * STAGE_BYTES, tid);
            asm volatile("cp.async.commit_group;" ::: "memory");
            asm volatile("cp.async.wait_group 1;" ::: "memory");
        } else {
            asm volatile("cp.async.wait_group 0;" ::: "memory");
        }
        __syncthreads();

        const float* As = (const float*)(smem_raw + buf * STAGE_BYTES);
        const float* Bs = As + TILE_FLOATS;

        #pragma unroll
        for (int k8 = 0; k8 < 4; k8++) {
            const int kk = k8 * 8;
            uint32_t af[2][4];
            #pragma unroll
            for (int i = 0; i < 2; i++) {
                int r = (mw + i * 16 + g) * PAD_STRIDE + kk;
                af[i][0] = f2tf32(As[r + t]);
                af[i][1] = f2tf32(As[r + 8 * PAD_STRIDE + t]);
                af[i][2] = f2tf32(As[r + t + 4]);
                af[i][3] = f2tf32(As[r + 8 * PAD_STRIDE + t + 4]);
            }
            uint32_t bf[8][2];
            #pragma unroll
            for (int j = 0; j < 8; j++) {
                int r = (nw + j * 8 + g) * PAD_STRIDE + kk;
                bf[j][0] = f2tf32(Bs[r + t]);
                bf[j][1] = f2tf32(Bs[r + t + 4]);
            }
            #pragma unroll
            for (int i = 0; i < 2; i++)
                #pragma unroll
                for (int j = 0; j < 8; j++)
                    mma_tf32(acc[i][j], af[i], bf[j]);
        }
        __syncthreads();
    }

    // ---- Epilogue: bias add, coalesced-ish float2 stores, BN stats ----
    #pragma unroll
    for (int j = 0; j < 8; j++) {
        const int cl = nw + j * 8 + 2 * t;        // local col in [0,128)
        const int cg = n0 + cl;                   // global col
        const float b0v = __ldg(&bias[cg]);
        const float b1v = __ldg(&bias[cg + 1]);
        float s0 = 0.f, s1 = 0.f, q0 = 0.f, q1 = 0.f;
        #pragma unroll
        for (int i = 0; i < 2; i++) {
            const int row = m0 + mw + i * 16 + g;
            float v00 = acc[i][j][0] + b0v;
            float v01 = acc[i][j][1] + b1v;
            float v10 = acc[i][j][2] + b0v;
            float v11 = acc[i][j][3] + b1v;
            float2 lo; lo.x = v00; lo.y = v01;
            float2 hi; hi.x = v10; hi.y = v11;
            *(float2*)&Cout[(size_t)row * C + cg] = lo;
            *(float2*)&Cout[(size_t)(row + 8) * C + cg] = hi;
            s0 += v00 + v10;  s1 += v01 + v11;
            q0 += v00 * v00 + v10 * v10;
            q1 += v01 * v01 + v11 * v11;
        }
        atomicAdd(&ssum[cl], s0);     atomicAdd(&ssum[cl + 1], s1);
        atomicAdd(&sssq[cl], q0);     atomicAdd(&sssq[cl + 1], q1);
    }
    __syncthreads();
    if (tid < 128) {
        atomicAdd(&sum[n0 + tid], ssum[tid]);
        atomicAdd(&ssq[n0 + tid], sssq[tid]);
    }
}

// ---------------------------------------------------------------------------
extern "C" void kernel_launch(void* const* d_in, const int* in_sizes, int n_in,
                              void* d_out, int out_size)
{
    const float* feat    = (const float*)d_in[0];   // [65536, 512]
    const float* skip    = (const float*)d_in[1];   // [262144, 256]
    const int*   cluster = (const int*)  d_in[2];   // [262144]
    const float* W_proj  = (const float*)d_in[3];   // [512, 256]
    const float* b_proj  = (const float*)d_in[4];
    const float* gamma_p = (const float*)d_in[5];
    const float* beta_p  = (const float*)d_in[6];
    const float* W_skip  = (const float*)d_in[7];   // [256, 256]
    const float* b_skip  = (const float*)d_in[8];
    const float* gamma_s = (const float*)d_in[9];
    const float* beta_s  = (const float*)d_in[10];
    float* out = (float*)d_out;

    float *h_ptr, *s_ptr, *wtp, *wts, *sum_p, *ssq_p, *sum_s, *ssq_s;
    cudaGetSymbolAddress((void**)&h_ptr, g_h);
    cudaGetSymbolAddress((void**)&s_ptr, g_s);
    cudaGetSymbolAddress((void**)&wtp, g_wt_proj);
    cudaGetSymbolAddress((void**)&wts, g_wt_skip);
    cudaGetSymbolAddress((void**)&sum_p, g_sum_p);
    cudaGetSymbolAddress((void**)&ssq_p, g_ssq_p);
    cudaGetSymbolAddress((void**)&sum_s, g_sum_s);
    cudaGetSymbolAddress((void**)&ssq_s, g_ssq_s);

    cudaFuncSetAttribute(mma_gemm_kernel,
                         cudaFuncAttributeMaxDynamicSharedMemorySize, SMEM_BYTES);

    zero_stats_kernel<<<1, 256>>>();

    transpose_w_kernel<<<dim3(256 / 32, 512 / 32), dim3(32, 8)>>>(W_proj, wtp, 512, 256);
    transpose_w_kernel<<<dim3(256 / 32, 256 / 32), dim3(32, 8)>>>(W_skip, wts, 256, 256);

    // GEMM1: g_h = feat @ W_proj + b_proj   (M=65536, K=512)
    mma_gemm_kernel<<<dim3(N_IN / 128, 2), 256, SMEM_BYTES>>>(
        feat, wtp, b_proj, h_ptr, 512, sum_p, ssq_p);

    // GEMM2: g_s = skip @ W_skip + b_skip   (M=262144, K=256)
    mma_gemm_kernel<<<dim3(N_OUT / 128, 2), 256, SMEM_BYTES>>>(
        skip, wts, b_skip, s_ptr, 256, sum_s, ssq_s);

    finalize_kernel<<<1, 256>>>(gamma_p, beta_p, gamma_s, beta_s);

    fuse_out_kernel<<<(N_OUT * 64) / 256, 256>>>(cluster, out);
}

// round 4
// speedup vs baseline: 1.7698x; 1.0141x over previous
#include <cuda_runtime.h>
#include <cstdint>

// ---------------------------------------------------------------------------
// UnpoolWithSkip — tf32 mma.sync GEMMs (no cvt: raw fp32 bits, HW truncates to
// tf32) + fused BN-stat epilogue. GEMM order: skip-branch first so g_h is
// L2-resident when the gather kernel runs.
//   h = relu(BN(feat @ W_proj + b_proj))          [65536, 256]
//   s = relu(BN(skip @ W_skip + b_skip))          [262144, 256]
//   out = h[cluster] + s                          [262144, 256]
// ---------------------------------------------------------------------------

#define EPS 1e-5f

static constexpr int N_IN  = 65536;
static constexpr int N_OUT = 262144;
static constexpr int C     = 256;

__device__ float g_h[(size_t)N_IN  * C];
__device__ float g_s[(size_t)N_OUT * C];
__device__ float g_wt_proj[(size_t)C * 512];
__device__ float g_wt_skip[(size_t)C * 256];
__device__ float g_sum_p[C], g_ssq_p[C];
__device__ float g_sum_s[C], g_ssq_s[C];
__device__ float g_a_p[C], g_b_p[C];
__device__ float g_a_s[C], g_b_s[C];

// ---------------------------------------------------------------------------
__device__ __forceinline__ uint32_t smem_u32(const void* p) {
    uint32_t a;
    asm("{ .reg .u64 t; cvta.to.shared.u64 t, %1; cvt.u32.u64 %0, t; }"
        : "=r"(a) : "l"(p));
    return a;
}
__device__ __forceinline__ void mma_tf32(float* c, const uint32_t* a, const uint32_t* b) {
    asm volatile(
        "mma.sync.aligned.m16n8k8.row.col.f32.tf32.tf32.f32 "
        "{%0,%1,%2,%3}, {%4,%5,%6,%7}, {%8,%9}, {%0,%1,%2,%3};"
        : "+f"(c[0]), "+f"(c[1]), "+f"(c[2]), "+f"(c[3])
        : "r"(a[0]), "r"(a[1]), "r"(a[2]), "r"(a[3]), "r"(b[0]), "r"(b[1]));
}

// ---------------------------------------------------------------------------
__global__ void zero_stats_kernel() {
    int c = threadIdx.x;
    g_sum_p[c] = 0.f; g_ssq_p[c] = 0.f;
    g_sum_s[c] = 0.f; g_ssq_s[c] = 0.f;
}

__global__ void transpose_w_kernel(const float* __restrict__ W,
                                   float* __restrict__ Wt, int K, int N) {
    __shared__ float t[32][33];
    int n0 = blockIdx.x * 32, k0 = blockIdx.y * 32;
    int tx = threadIdx.x, ty = threadIdx.y;
    #pragma unroll
    for (int i = 0; i < 32; i += 8)
        t[ty + i][tx] = W[(size_t)(k0 + ty + i) * N + n0 + tx];
    __syncthreads();
    #pragma unroll
    for (int i = 0; i < 32; i += 8)
        Wt[(size_t)(n0 + ty + i) * K + k0 + tx] = t[tx][ty + i];
}

__global__ void finalize_kernel(
    const float* __restrict__ gamma_p, const float* __restrict__ beta_p,
    const float* __restrict__ gamma_s, const float* __restrict__ beta_s)
{
    int c = threadIdx.x;
    {
        float m = g_sum_p[c] * (1.f / N_IN);
        float v = g_ssq_p[c] * (1.f / N_IN) - m * m;
        float a = gamma_p[c] * rsqrtf(v + EPS);
        g_a_p[c] = a; g_b_p[c] = beta_p[c] - m * a;
    }
    {
        float m = g_sum_s[c] * (1.f / N_OUT);
        float v = g_ssq_s[c] * (1.f / N_OUT) - m * m;
        float a = gamma_s[c] * rsqrtf(v + EPS);
        g_a_s[c] = a; g_b_s[c] = beta_s[c] - m * a;
    }
}

__global__ __launch_bounds__(256) void fuse_out_kernel(
    const int* __restrict__ cluster, float* __restrict__ out)
{
    int idx = blockIdx.x * 256 + threadIdx.x;
    int n  = idx >> 6;
    int c4 = (idx & 63) << 2;
    int k  = __ldg(&cluster[n]);

    float4 h  = *(const float4*)&g_h[(size_t)k * C + c4];
    float4 sv = *(const float4*)&g_s[(size_t)n * C + c4];
    float4 ap = *(const float4*)&g_a_p[c4];
    float4 bp = *(const float4*)&g_b_p[c4];
    float4 as_ = *(const float4*)&g_a_s[c4];
    float4 bs_ = *(const float4*)&g_b_s[c4];

    float4 o;
    o.x = fmaxf(fmaf(ap.x, h.x, bp.x), 0.f) + fmaxf(fmaf(as_.x, sv.x, bs_.x), 0.f);
    o.y = fmaxf(fmaf(ap.y, h.y, bp.y), 0.f) + fmaxf(fmaf(as_.y, sv.y, bs_.y), 0.f);
    o.z = fmaxf(fmaf(ap.z, h.z, bp.z), 0.f) + fmaxf(fmaf(as_.z, sv.z, bs_.z), 0.f);
    o.w = fmaxf(fmaf(ap.w, h.w, bp.w), 0.f) + fmaxf(fmaf(as_.w, sv.w, bs_.w), 0.f);
    *(float4*)&out[(size_t)n * C + c4] = o;
}

// ---------------------------------------------------------------------------
// tf32 mma.sync GEMM: C[M,256] = A[M,K] @ Bt[256,K]^T + bias, + per-channel
// sum/sumsq. Tile 128x128, BK=32, 256 threads (warps 4x2 -> 32x64 each).
// cp.async double-buffered. Grid (M/128, 2). No tf32 rounding (truncate).
// ---------------------------------------------------------------------------
static constexpr int PAD_STRIDE = 36;
static constexpr int TILE_FLOATS = 128 * PAD_STRIDE;
static constexpr uint32_t A_BYTES = TILE_FLOATS * 4;
static constexpr uint32_t STAGE_BYTES = A_BYTES * 2;
static constexpr uint32_t SMEM_BYTES = STAGE_BYTES * 2;

__device__ __forceinline__ void load_tile_async(
    const float* __restrict__ A, const float* __restrict__ Bt, int K,
    int m0, int n0, int kt, uint32_t sbase, int tid)
{
    #pragma unroll
    for (int p = 0; p < 4; p++) {
        int idx = tid + p * 256;
        int row = idx >> 3, ch = idx & 7;
        const float* ga = A + (size_t)(m0 + row) * K + kt * 32 + ch * 4;
        uint32_t sa = sbase + row * (PAD_STRIDE * 4) + ch * 16;
        asm volatile("cp.async.cg.shared.global [%0], [%1], 16;"
                     :: "r"(sa), "l"(ga) : "memory");
        const float* gb = Bt + (size_t)(n0 + row) * K + kt * 32 + ch * 4;
        uint32_t sb = sbase + A_BYTES + row * (PAD_STRIDE * 4) + ch * 16;
        asm volatile("cp.async.cg.shared.global [%0], [%1], 16;"
                     :: "r"(sb), "l"(gb) : "memory");
    }
}

__global__ __launch_bounds__(256) void mma_gemm_kernel(
    const float* __restrict__ A, const float* __restrict__ Bt,
    const float* __restrict__ bias, float* __restrict__ Cout,
    int K, float* __restrict__ sum, float* __restrict__ ssq)
{
    extern __shared__ char smem_raw[];
    __shared__ float ssum[128], sssq[128];

    const int tid  = threadIdx.x;
    const int lane = tid & 31;
    const int wid  = tid >> 5;
    const int wm   = wid & 3;
    const int wn   = wid >> 2;
    const int g    = lane >> 2;
    const int t    = lane & 3;

    const int m0 = blockIdx.x * 128;
    const int n0 = blockIdx.y * 128;

    const uint32_t sbase = smem_u32(smem_raw);

    if (tid < 128) { ssum[tid] = 0.f; sssq[tid] = 0.f; }

    float acc[2][8][4];
    #pragma unroll
    for (int i = 0; i < 2; i++)
        #pragma unroll
        for (int j = 0; j < 8; j++)
            #pragma unroll
            for (int q = 0; q < 4; q++) acc[i][j][q] = 0.f;

    const int KT = K >> 5;

    load_tile_async(A, Bt, K, m0, n0, 0, sbase, tid);
    asm volatile("cp.async.commit_group;" ::: "memory");

    const int mw = wm * 32;
    const int nw = wn * 64;

    for (int kt = 0; kt < KT; kt++) {
        const int buf = kt & 1;
        if (kt + 1 < KT) {
            load_tile_async(A, Bt, K, m0, n0, kt + 1,
                            sbase + (buf ^ 1) * STAGE_BYTES, tid);
            asm volatile("cp.async.commit_group;" ::: "memory");
            asm volatile("cp.async.wait_group 1;" ::: "memory");
        } else {
            asm volatile("cp.async.wait_group 0;" ::: "memory");
        }
        __syncthreads();

        const uint32_t* As = (const uint32_t*)(smem_raw + buf * STAGE_BYTES);
        const uint32_t* Bs = As + TILE_FLOATS;

        #pragma unroll
        for (int k8 = 0; k8 < 4; k8++) {
            const int kk = k8 * 8;
            uint32_t af[2][4];
            #pragma unroll
            for (int i = 0; i < 2; i++) {
                int r = (mw + i * 16 + g) * PAD_STRIDE + kk;
                af[i][0] = As[r + t];
                af[i][1] = As[r + 8 * PAD_STRIDE + t];
                af[i][2] = As[r + t + 4];
                af[i][3] = As[r + 8 * PAD_STRIDE + t + 4];
            }
            uint32_t bf[8][2];
            #pragma unroll
            for (int j = 0; j < 8; j++) {
                int r = (nw + j * 8 + g) * PAD_STRIDE + kk;
                bf[j][0] = Bs[r + t];
                bf[j][1] = Bs[r + t + 4];
            }
            #pragma unroll
            for (int i = 0; i < 2; i++)
                #pragma unroll
                for (int j = 0; j < 8; j++)
                    mma_tf32(acc[i][j], af[i], bf[j]);
        }
        __syncthreads();
    }

    // ---- Epilogue: bias add, float2 stores (sector-aligned), BN stats ----
    #pragma unroll
    for (int j = 0; j < 8; j++) {
        const int cl = nw + j * 8 + 2 * t;
        const int cg = n0 + cl;
        const float b0v = __ldg(&bias[cg]);
        const float b1v = __ldg(&bias[cg + 1]);
        float s0 = 0.f, s1 = 0.f, q0 = 0.f, q1 = 0.f;
        #pragma unroll
        for (int i = 0; i < 2; i++) {
            const int row = m0 + mw + i * 16 + g;
            float v00 = acc[i][j][0] + b0v;
            float v01 = acc[i][j][1] + b1v;
            float v10 = acc[i][j][2] + b0v;
            float v11 = acc[i][j][3] + b1v;
            float2 lo; lo.x = v00; lo.y = v01;
            float2 hi; hi.x = v10; hi.y = v11;
            *(float2*)&Cout[(size_t)row * C + cg] = lo;
            *(float2*)&Cout[(size_t)(row + 8) * C + cg] = hi;
            s0 += v00 + v10;  s1 += v01 + v11;
            q0 += v00 * v00 + v10 * v10;
            q1 += v01 * v01 + v11 * v11;
        }
        atomicAdd(&ssum[cl], s0);     atomicAdd(&ssum[cl + 1], s1);
        atomicAdd(&sssq[cl], q0);     atomicAdd(&sssq[cl + 1], q1);
    }
    __syncthreads();
    if (tid < 128) {
        atomicAdd(&sum[n0 + tid], ssum[tid]);
        atomicAdd(&ssq[n0 + tid], sssq[tid]);
    }
}

// ---------------------------------------------------------------------------
extern "C" void kernel_launch(void* const* d_in, const int* in_sizes, int n_in,
                              void* d_out, int out_size)
{
    const float* feat    = (const float*)d_in[0];   // [65536, 512]
    const float* skip    = (const float*)d_in[1];   // [262144, 256]
    const int*   cluster = (const int*)  d_in[2];   // [262144]
    const float* W_proj  = (const float*)d_in[3];   // [512, 256]
    const float* b_proj  = (const float*)d_in[4];
    const float* gamma_p = (const float*)d_in[5];
    const float* beta_p  = (const float*)d_in[6];
    const float* W_skip  = (const float*)d_in[7];   // [256, 256]
    const float* b_skip  = (const float*)d_in[8];
    const float* gamma_s = (const float*)d_in[9];
    const float* beta_s  = (const float*)d_in[10];
    float* out = (float*)d_out;

    float *h_ptr, *s_ptr, *wtp, *wts, *sum_p, *ssq_p, *sum_s, *ssq_s;
    cudaGetSymbolAddress((void**)&h_ptr, g_h);
    cudaGetSymbolAddress((void**)&s_ptr, g_s);
    cudaGetSymbolAddress((void**)&wtp, g_wt_proj);
    cudaGetSymbolAddress((void**)&wts, g_wt_skip);
    cudaGetSymbolAddress((void**)&sum_p, g_sum_p);
    cudaGetSymbolAddress((void**)&ssq_p, g_ssq_p);
    cudaGetSymbolAddress((void**)&sum_s, g_sum_s);
    cudaGetSymbolAddress((void**)&ssq_s, g_ssq_s);

    cudaFuncSetAttribute(mma_gemm_kernel,
                         cudaFuncAttributeMaxDynamicSharedMemorySize, SMEM_BYTES);

    zero_stats_kernel<<<1, 256>>>();

    transpose_w_kernel<<<dim3(256 / 32, 512 / 32), dim3(32, 8)>>>(W_proj, wtp, 512, 256);
    transpose_w_kernel<<<dim3(256 / 32, 256 / 32), dim3(32, 8)>>>(W_skip, wts, 256, 256);

    // GEMM2 first (big, streams through L2), then GEMM1 so g_h stays L2-warm
    // for the gather in fuse_out.
    mma_gemm_kernel<<<dim3(N_OUT / 128, 2), 256, SMEM_BYTES>>>(
        skip, wts, b_skip, s_ptr, 256, sum_s, ssq_s);

    mma_gemm_kernel<<<dim3(N_IN / 128, 2), 256, SMEM_BYTES>>>(
        feat, wtp, b_proj, h_ptr, 512, sum_p, ssq_p);

    finalize_kernel<<<1, 256>>>(gamma_p, beta_p, gamma_s, beta_s);

    fuse_out_kernel<<<(N_OUT * 64) / 256, 256>>>(cluster, out);
}